// round 2
// baseline (speedup 1.0000x reference)
#include <cuda_runtime.h>
#include <cuda_bf16.h>
#include <cstdint>

// Problem constants (match reference)
#define NN      50000
#define NODE_F  192
#define EDGE_F  64
#define MM      800000
#define DD      256
#define OUTF    2048
#define DEPTH   3

// ---------------- scratch (static device globals; no allocation) -------------
__device__ float g_attr[(size_t)NN * DD];          // 51.2 MB
__device__ float g_v[(size_t)NN * DD];             // 51.2 MB
__device__ float g_logits[(size_t)NN * OUTF];      // 409.6 MB

// ---------------- tiny utility kernels ---------------------------------------
__global__ void zero_fp_kernel(float* fp) {
    int i = threadIdx.x + blockIdx.x * blockDim.x;
    if (i < OUTF) fp[i] = 0.0f;
}

__global__ void init_attr_kernel(const float* __restrict__ node_attr,
                                 float* __restrict__ attr, int n) {
    int idx = threadIdx.x + blockIdx.x * blockDim.x;
    int total = n * DD;
    if (idx >= total) return;
    int i = idx >> 8;          // / 256
    int k = idx & 255;
    attr[idx] = (k < NODE_F) ? node_attr[i * NODE_F + k] : 0.0f;
}

__global__ void copy_v_kernel(const float4* __restrict__ src,
                              float4* __restrict__ dst, int n4) {
    int idx = threadIdx.x + blockIdx.x * blockDim.x;
    if (idx < n4) dst[idx] = src[idx];
}

// ---------------- edge message + scatter -------------------------------------
// one thread per (edge, float4-chunk); 64 chunks per edge (D=256)
__global__ void edge_msg_kernel(const float* __restrict__ attr,
                                const float* __restrict__ edge_attr,
                                const int* __restrict__ esrc,
                                const int* __restrict__ edst,
                                float* __restrict__ v, int m) {
    long long idx = (long long)blockIdx.x * blockDim.x + threadIdx.x;
    long long total = (long long)m * 64;
    if (idx >= total) return;
    int e = (int)(idx >> 6);
    int c = (int)(idx & 63);
    int s = esrc[e];
    int d = edst[e];
    const float4* a4 = (const float4*)attr;
    float4 val = a4[(size_t)s * 64 + c];
    if (c >= 48) {  // edge feature region: cols [192,256) -> chunks [48,64)
        const float4* e4 = (const float4*)edge_attr;
        float4 ea = e4[(size_t)e * 16 + (c - 48)];
        val.x += ea.x; val.y += ea.y; val.z += ea.z; val.w += ea.w;
    }
    float* vd = v + (size_t)d * DD + c * 4;
    atomicAdd(vd + 0, val.x);
    atomicAdd(vd + 1, val.y);
    atomicAdd(vd + 2, val.z);
    atomicAdd(vd + 3, val.w);
}

// ---------------- fp32 SGEMM with bias: C[M,Nc] = A[M,256] * B[256,Nc] + bias --
// 128x128 tile, BK=8, 256 threads, 8x8 micro-tile per thread
__global__ __launch_bounds__(256) void sgemm_bias_kernel(
        const float* __restrict__ A, const float* __restrict__ B,
        const float* __restrict__ bias, float* __restrict__ C,
        int Mrows, int Ncols) {
    __shared__ float As[8][128];
    __shared__ float Bs[8][128];

    const int tid = threadIdx.x;
    const int block_row = blockIdx.y * 128;
    const int block_col = blockIdx.x * 128;

    // A tile loader: row = tid/2 (0..127), col4 = (tid%2)*4
    const int a_row = tid >> 1;
    const int a_col = (tid & 1) * 4;
    // B tile loader: row = tid/32 (0..7), col4 = (tid%32)*4
    const int b_row = tid >> 5;
    const int b_col = (tid & 31) * 4;

    const int tx = tid & 15;    // 0..15 -> 8 cols each
    const int ty = tid >> 4;    // 0..15 -> 8 rows each

    float acc[8][8];
#pragma unroll
    for (int i = 0; i < 8; i++)
#pragma unroll
        for (int j = 0; j < 8; j++) acc[i][j] = 0.0f;

    const int grA = block_row + a_row;
    const bool a_valid = (grA < Mrows);
    const float* Aptr = A + (size_t)grA * 256 + a_col;
    const float* Bptr = B + (size_t)b_row * Ncols + block_col + b_col;

    for (int k0 = 0; k0 < 256; k0 += 8) {
        float4 av = make_float4(0.f, 0.f, 0.f, 0.f);
        if (a_valid) av = *(const float4*)(Aptr + k0);
        As[a_col + 0][a_row] = av.x;
        As[a_col + 1][a_row] = av.y;
        As[a_col + 2][a_row] = av.z;
        As[a_col + 3][a_row] = av.w;

        float4 bv = *(const float4*)(Bptr + (size_t)k0 * Ncols);
        *(float4*)&Bs[b_row][b_col] = bv;

        __syncthreads();

#pragma unroll
        for (int k = 0; k < 8; k++) {
            float ra[8], rb[8];
#pragma unroll
            for (int i = 0; i < 8; i++) ra[i] = As[k][ty * 8 + i];
#pragma unroll
            for (int j = 0; j < 8; j++) rb[j] = Bs[k][tx * 8 + j];
#pragma unroll
            for (int i = 0; i < 8; i++)
#pragma unroll
                for (int j = 0; j < 8; j++) acc[i][j] += ra[i] * rb[j];
        }
        __syncthreads();
    }

    // epilogue: add bias, store
    float bb[8];
#pragma unroll
    for (int j = 0; j < 8; j++) bb[j] = bias[block_col + tx * 8 + j];

#pragma unroll
    for (int i = 0; i < 8; i++) {
        int r = block_row + ty * 8 + i;
        if (r < Mrows) {
            float* crow = C + (size_t)r * Ncols + block_col + tx * 8;
            float4 v0, v1;
            v0.x = acc[i][0] + bb[0];
            v0.y = acc[i][1] + bb[1];
            v0.z = acc[i][2] + bb[2];
            v0.w = acc[i][3] + bb[3];
            v1.x = acc[i][4] + bb[4];
            v1.y = acc[i][5] + bb[5];
            v1.z = acc[i][6] + bb[6];
            v1.w = acc[i][7] + bb[7];
            *(float4*)(crow + 0) = v0;
            *(float4*)(crow + 4) = v1;
        }
    }
}

// ---------------- softmax over rows of logits + accumulate into fp ------------
// 256 threads, each block handles NB=32 node rows serially; fp staged in smem.
#define NB_SM 32
__global__ __launch_bounds__(256) void softmax_accum_kernel(
        const float* __restrict__ logits, float* __restrict__ fp, int nrows) {
    __shared__ float sfp[OUTF];
    __shared__ float sredm[8];
    __shared__ float sreds[8];

    const int tid = threadIdx.x;
    const int lane = tid & 31;
    const int wid = tid >> 5;

    for (int i = tid; i < OUTF; i += 256) sfp[i] = 0.0f;
    __syncthreads();

    const int base = blockIdx.x * NB_SM;
    for (int r = 0; r < NB_SM; r++) {
        int node = base + r;
        if (node >= nrows) break;
        const float* row = logits + (size_t)node * OUTF;

        float v[8];
#pragma unroll
        for (int j = 0; j < 8; j++) v[j] = row[tid + j * 256];

        // block max
        float m = v[0];
#pragma unroll
        for (int j = 1; j < 8; j++) m = fmaxf(m, v[j]);
#pragma unroll
        for (int o = 16; o; o >>= 1) m = fmaxf(m, __shfl_xor_sync(0xffffffffu, m, o));
        if (lane == 0) sredm[wid] = m;
        __syncthreads();
        m = sredm[0];
#pragma unroll
        for (int w = 1; w < 8; w++) m = fmaxf(m, sredm[w]);

        // exp + block sum
        float e[8];
        float s = 0.0f;
#pragma unroll
        for (int j = 0; j < 8; j++) { e[j] = __expf(v[j] - m); s += e[j]; }
#pragma unroll
        for (int o = 16; o; o >>= 1) s += __shfl_xor_sync(0xffffffffu, s, o);
        if (lane == 0) sreds[wid] = s;
        __syncthreads();
        float st = 0.0f;
#pragma unroll
        for (int w = 0; w < 8; w++) st += sreds[w];
        float inv = 1.0f / st;

#pragma unroll
        for (int j = 0; j < 8; j++) sfp[tid + j * 256] += e[j] * inv;
        __syncthreads();  // protect sredm/sreds reuse next iteration
    }

    for (int i = tid; i < OUTF; i += 256) atomicAdd(&fp[i], sfp[i]);
}

// ---------------- launch ------------------------------------------------------
extern "C" void kernel_launch(void* const* d_in, const int* in_sizes, int n_in,
                              void* d_out, int out_size) {
    const float* node_attr = (const float*)d_in[0];
    const float* edge_attr = (const float*)d_in[1];
    const int*   edge_src  = (const int*)d_in[2];
    const int*   edge_dst  = (const int*)d_in[3];
    const float* W_inner   = (const float*)d_in[4];
    const float* b_inner   = (const float*)d_in[5];
    const float* W_output  = (const float*)d_in[6];
    const float* b_output  = (const float*)d_in[7];
    float* fp = (float*)d_out;

    const int n = in_sizes[0] / NODE_F;   // 50000
    const int m = in_sizes[2];            // 800000

    float *attr, *v, *logits;
    cudaGetSymbolAddress((void**)&attr,   g_attr);
    cudaGetSymbolAddress((void**)&v,      g_v);
    cudaGetSymbolAddress((void**)&logits, g_logits);

    const int blocksM = (n + 127) / 128;
    dim3 gemm_out_grid(OUTF / 128, blocksM);
    dim3 gemm_inner_grid(DD / 128, blocksM);
    const int sm_blocks = (n + NB_SM - 1) / NB_SM;

    zero_fp_kernel<<<(OUTF + 255) / 256, 256>>>(fp);
    init_attr_kernel<<<(n * DD + 255) / 256, 256>>>(node_attr, attr, n);

    // depth-0 fingerprint contribution
    sgemm_bias_kernel<<<gemm_out_grid, 256>>>(attr, W_output, b_output, logits, n, OUTF);
    softmax_accum_kernel<<<sm_blocks, 256>>>(logits, fp, n);

    for (int d = 1; d <= DEPTH; d++) {
        // v = attr
        copy_v_kernel<<<(n * 64 + 255) / 256, 256>>>((const float4*)attr, (float4*)v, n * 64);
        // v += scatter(attr[src] + edge_pad)
        long long etotal = (long long)m * 64;
        int eblocks = (int)((etotal + 255) / 256);
        edge_msg_kernel<<<eblocks, 256>>>(attr, edge_attr, edge_src, edge_dst, v, m);
        // attr = v @ W_inner[d-1] + b_inner[d-1]
        sgemm_bias_kernel<<<gemm_inner_grid, 256>>>(
            v, W_inner + (size_t)(d - 1) * DD * DD, b_inner + (size_t)(d - 1) * DD,
            attr, n, DD);
        // fp += softmax(attr @ W_output[d] + b_output[d]).sum(0)
        sgemm_bias_kernel<<<gemm_out_grid, 256>>>(
            attr, W_output + (size_t)d * DD * OUTF, b_output + (size_t)d * OUTF,
            logits, n, OUTF);
        softmax_accum_kernel<<<sm_blocks, 256>>>(logits, fp, n);
    }
}

// round 9
// speedup vs baseline: 1.5684x; 1.5684x over previous
#include <cuda_runtime.h>
#include <cuda_bf16.h>
#include <cstdint>

// Problem constants
#define NN      50000
#define NODE_F  192
#define EDGE_F  64
#define MM      800000
#define DD      256
#define OUTF    2048
#define DEPTH   3

// ---------------- scratch (static device globals; no allocation) -------------
__device__ float g_attr[(size_t)NN * DD];                 // 51.2 MB fp32
__device__ float g_v[(size_t)NN * DD];                    // 51.2 MB fp32
__device__ float g_logits[(size_t)NN * OUTF];             // 409.6 MB fp32
__device__ __nv_bfloat16 g_Asplit[2 * (size_t)NN * DD];   // 51.2 MB  [split][NN*256]
__device__ __nv_bfloat16 g_Bout[(size_t)(DEPTH + 1) * 2 * OUTF * DD]; // 8.4 MB
__device__ __nv_bfloat16 g_Binn[(size_t)DEPTH * 2 * DD * DD];         // 0.8 MB

// ================= small PTX helpers =========================================
__device__ __forceinline__ uint32_t smem_u32(const void* p) {
    uint32_t a;
    asm("{ .reg .u64 t; cvta.to.shared.u64 t, %1; cvt.u32.u64 %0, t; }"
        : "=r"(a) : "l"(p));
    return a;
}
__device__ __forceinline__ void cpa16(uint32_t saddr, const void* g, int srcsz) {
    asm volatile("cp.async.cg.shared.global [%0], [%1], 16, %2;"
                 :: "r"(saddr), "l"(g), "r"(srcsz));
}
#define CPA_COMMIT() asm volatile("cp.async.commit_group;" ::: "memory")
#define SWZ128(off) ((off) ^ (((off) >> 3) & 0x70))

__device__ __forceinline__ void ldsm_x4(uint32_t& r0, uint32_t& r1,
                                        uint32_t& r2, uint32_t& r3, uint32_t a) {
    asm volatile("ldmatrix.sync.aligned.m8n8.x4.shared.b16 {%0,%1,%2,%3}, [%4];"
                 : "=r"(r0), "=r"(r1), "=r"(r2), "=r"(r3) : "r"(a));
}
__device__ __forceinline__ void ldsm_x2(uint32_t& r0, uint32_t& r1, uint32_t a) {
    asm volatile("ldmatrix.sync.aligned.m8n8.x2.shared.b16 {%0,%1}, [%2];"
                 : "=r"(r0), "=r"(r1) : "r"(a));
}
__device__ __forceinline__ void mma16816(float* d, const uint32_t* a,
                                         const uint32_t* b) {
    asm volatile("mma.sync.aligned.m16n8k16.row.col.f32.bf16.bf16.f32 "
                 "{%0,%1,%2,%3}, {%4,%5,%6,%7}, {%8,%9}, {%0,%1,%2,%3};"
                 : "+f"(d[0]), "+f"(d[1]), "+f"(d[2]), "+f"(d[3])
                 : "r"(a[0]), "r"(a[1]), "r"(a[2]), "r"(a[3]),
                   "r"(b[0]), "r"(b[1]));
}

// ================= bf16 split-3 GEMM via mma.sync (HMMA) ======================
// C[M,Nc] = A_fp32[M,256] @ B_fp32[256,Nc] + bias, via 3 bf16 split-pair passes
// fused into one K-loop of 12 chunks (BK=64). A: [2][NN*256] row-major.
// B: [2][Nc*256] (n-major rows, K contiguous).
#define KCH 64
#define TILE_BYTES (128 * 128)          // 128 rows x 128B (64 bf16)
#define STAGE_B (2 * TILE_BYTES)        // A tile + B tile
#define NCHUNK 12
#define GEMM_DSMEM (1024 + 2 * STAGE_B) // ~66 KB

__global__ __launch_bounds__(256, 2) void hmma_gemm_kernel(
        const __nv_bfloat16* __restrict__ A,
        const __nv_bfloat16* __restrict__ B,
        const float* __restrict__ bias,
        float* __restrict__ C, int Mrows, int Ncols) {
    extern __shared__ char dsm_raw[];
    __shared__ float s_bias[128];

    const int tid = threadIdx.x;
    const int wid = tid >> 5;
    const int lane = tid & 31;
    const int block_row = blockIdx.y * 128;
    const int block_col = blockIdx.x * 128;

    uint32_t dsm = smem_u32(dsm_raw);
    dsm = (dsm + 1023u) & ~1023u;

    if (tid < 128) s_bias[tid] = bias[block_col + tid];

    // warp tiling: wm in {0,1} selects 64 M-rows, wn in {0..3} selects 32 N-cols
    const int wm = wid & 1;
    const int wn = wid >> 1;

    const int sa_tab[3] = {0, 0, 1};
    const int sb_tab[3] = {0, 1, 0};
    const size_t a_split_stride = (size_t)NN * DD;
    const size_t b_split_stride = (size_t)Ncols * DD;

    float acc[4][4][4];
#pragma unroll
    for (int i = 0; i < 4; i++)
#pragma unroll
        for (int j = 0; j < 4; j++)
#pragma unroll
            for (int k = 0; k < 4; k++) acc[i][j][k] = 0.0f;

    // loader: thread t handles row t/2, half (t&1) of the 128B row (4x16B)
    const int ld_row = tid >> 1;
    const int ld_half = tid & 1;

    auto load_chunk = [&](int chunk, int stage) {
        int p = chunk >> 2;
        int k0 = (chunk & 3) * KCH;
        uint32_t stA = dsm + stage * STAGE_B;
        uint32_t stB = stA + TILE_BYTES;
        // A tile
        {
            int grow = block_row + ld_row;
            int sz = (grow < Mrows) ? 16 : 0;
            if (grow >= Mrows) grow = 0;
            const __nv_bfloat16* gsrc =
                A + sa_tab[p] * a_split_stride + (size_t)grow * DD + k0 + ld_half * 32;
#pragma unroll
            for (int t = 0; t < 4; t++) {
                uint32_t off = ld_row * 128 + ld_half * 64 + t * 16;
                cpa16(stA + SWZ128(off), gsrc + t * 8, sz);
            }
        }
        // B tile (Ncols is a multiple of 128 -> always valid)
        {
            int grow = block_col + ld_row;
            const __nv_bfloat16* gsrc =
                B + sb_tab[p] * b_split_stride + (size_t)grow * DD + k0 + ld_half * 32;
#pragma unroll
            for (int t = 0; t < 4; t++) {
                uint32_t off = ld_row * 128 + ld_half * 64 + t * 16;
                cpa16(stB + SWZ128(off), gsrc + t * 8, 16);
            }
        }
        CPA_COMMIT();
    };

    load_chunk(0, 0);
    load_chunk(1, 1);

    for (int i = 0; i < NCHUNK; i++) {
        int s = i & 1;
        if (i < NCHUNK - 1) asm volatile("cp.async.wait_group 1;" ::: "memory");
        else                asm volatile("cp.async.wait_group 0;" ::: "memory");
        __syncthreads();

        uint32_t stA = dsm + s * STAGE_B;
        uint32_t stB = stA + TILE_BYTES;

#pragma unroll
        for (int k = 0; k < 4; k++) {   // 4 k-steps of 16 within BK=64
            uint32_t af[4][4], bf[4][2];
#pragma unroll
            for (int mt = 0; mt < 4; mt++) {
                int arow = wm * 64 + mt * 16 + (lane & 15);
                uint32_t off = arow * 128 + k * 32 + ((lane >> 4) & 1) * 16;
                ldsm_x4(af[mt][0], af[mt][1], af[mt][2], af[mt][3],
                        stA + SWZ128(off));
            }
#pragma unroll
            for (int nt = 0; nt < 4; nt++) {
                int nrow = wn * 32 + nt * 8 + (lane & 7);
                uint32_t off = nrow * 128 + k * 32 + ((lane >> 3) & 1) * 16;
                ldsm_x2(bf[nt][0], bf[nt][1], stB + SWZ128(off));
            }
#pragma unroll
            for (int mt = 0; mt < 4; mt++)
#pragma unroll
                for (int nt = 0; nt < 4; nt++)
                    mma16816(acc[mt][nt], af[mt], bf[nt]);
        }
        __syncthreads();               // everyone done reading stage s
        if (i + 2 < NCHUNK) load_chunk(i + 2, s);
    }

    // epilogue: acc layout per mma: d0,d1 -> row (lane>>2), cols 2*(lane&3)+{0,1}
    //           d2,d3 -> row (lane>>2)+8
    const int gid = lane >> 2;
    const int tig = lane & 3;
#pragma unroll
    for (int mt = 0; mt < 4; mt++) {
#pragma unroll
        for (int half = 0; half < 2; half++) {
            int r = block_row + wm * 64 + mt * 16 + gid + half * 8;
            if (r < Mrows) {
                float* crow = C + (size_t)r * Ncols + block_col;
#pragma unroll
                for (int nt = 0; nt < 4; nt++) {
                    int c = wn * 32 + nt * 8 + tig * 2;
                    float2 v;
                    v.x = acc[mt][nt][half * 2 + 0] + s_bias[c + 0];
                    v.y = acc[mt][nt][half * 2 + 1] + s_bias[c + 1];
                    *(float2*)(crow + c) = v;
                }
            }
        }
    }
}

// ================= split / conversion kernels =================================
__global__ void split_attr_kernel(const float* __restrict__ src,
                                  __nv_bfloat16* __restrict__ a0,
                                  __nv_bfloat16* __restrict__ a1, int total) {
    int i = blockIdx.x * blockDim.x + threadIdx.x;
    if (i >= total) return;
    float x = src[i];
    __nv_bfloat16 b0 = __float2bfloat16(x);
    float res = x - __bfloat162float(b0);
    a0[i] = b0;
    a1[i] = __float2bfloat16(res);
}

// W [256][Ncols] fp32 -> b0,b1 [Ncols][256] bf16 (transposed, K-major)
__global__ void split_w_kernel(const float* __restrict__ W,
                               __nv_bfloat16* __restrict__ b0,
                               __nv_bfloat16* __restrict__ b1, int Ncols) {
    int i = blockIdx.x * blockDim.x + threadIdx.x;
    if (i >= Ncols * DD) return;
    int nc = i >> 8;
    int k = i & 255;
    float x = W[(size_t)k * Ncols + nc];
    __nv_bfloat16 v0 = __float2bfloat16(x);
    float res = x - __bfloat162float(v0);
    b0[i] = v0;
    b1[i] = __float2bfloat16(res);
}

// ================= misc kernels ===============================================
__global__ void zero_fp_kernel(float* fp) {
    int i = threadIdx.x + blockIdx.x * blockDim.x;
    if (i < OUTF) fp[i] = 0.0f;
}

__global__ void init_attr_kernel(const float* __restrict__ node_attr,
                                 float* __restrict__ attr, int n) {
    int idx = threadIdx.x + blockIdx.x * blockDim.x;
    int total = n * DD;
    if (idx >= total) return;
    int i = idx >> 8;
    int k = idx & 255;
    attr[idx] = (k < NODE_F) ? node_attr[i * NODE_F + k] : 0.0f;
}

__global__ void copy_v_kernel(const float4* __restrict__ src,
                              float4* __restrict__ dst, int n4) {
    int idx = threadIdx.x + blockIdx.x * blockDim.x;
    if (idx < n4) dst[idx] = src[idx];
}

__global__ void edge_msg_kernel(const float* __restrict__ attr,
                                const float* __restrict__ edge_attr,
                                const int* __restrict__ esrc,
                                const int* __restrict__ edst,
                                float* __restrict__ v, int m) {
    long long idx = (long long)blockIdx.x * blockDim.x + threadIdx.x;
    long long total = (long long)m * 64;
    if (idx >= total) return;
    int e = (int)(idx >> 6);
    int c = (int)(idx & 63);
    int s = __ldg(esrc + e);
    int d = __ldg(edst + e);
    const float4* a4 = (const float4*)attr;
    float4 val = a4[(size_t)s * 64 + c];
    if (c >= 48) {
        const float4* e4 = (const float4*)edge_attr;
        float4 ea = e4[(size_t)e * 16 + (c - 48)];
        val.x += ea.x; val.y += ea.y; val.z += ea.z; val.w += ea.w;
    }
    float* vd = v + (size_t)d * DD + c * 4;
    atomicAdd(vd + 0, val.x);
    atomicAdd(vd + 1, val.y);
    atomicAdd(vd + 2, val.z);
    atomicAdd(vd + 3, val.w);
}

#define NB_SM 32
__global__ __launch_bounds__(256) void softmax_accum_kernel(
        const float* __restrict__ logits, float* __restrict__ fp, int nrows) {
    __shared__ float sfp[OUTF];
    __shared__ float sredm[8];
    __shared__ float sreds[8];

    const int tid = threadIdx.x;
    const int lane = tid & 31;
    const int wid = tid >> 5;

    for (int i = tid; i < OUTF; i += 256) sfp[i] = 0.0f;
    __syncthreads();

    const int base = blockIdx.x * NB_SM;
    for (int r = 0; r < NB_SM; r++) {
        int node = base + r;
        if (node >= nrows) break;
        const float* row = logits + (size_t)node * OUTF;

        float v[8];
#pragma unroll
        for (int j = 0; j < 8; j++) v[j] = row[tid + j * 256];

        float m = v[0];
#pragma unroll
        for (int j = 1; j < 8; j++) m = fmaxf(m, v[j]);
#pragma unroll
        for (int o = 16; o; o >>= 1) m = fmaxf(m, __shfl_xor_sync(0xffffffffu, m, o));
        if (lane == 0) sredm[wid] = m;
        __syncthreads();
        m = sredm[0];
#pragma unroll
        for (int w = 1; w < 8; w++) m = fmaxf(m, sredm[w]);

        float e[8];
        float s = 0.0f;
#pragma unroll
        for (int j = 0; j < 8; j++) { e[j] = __expf(v[j] - m); s += e[j]; }
#pragma unroll
        for (int o = 16; o; o >>= 1) s += __shfl_xor_sync(0xffffffffu, s, o);
        if (lane == 0) sreds[wid] = s;
        __syncthreads();
        float st = 0.0f;
#pragma unroll
        for (int w = 0; w < 8; w++) st += sreds[w];
        float inv = 1.0f / st;

#pragma unroll
        for (int j = 0; j < 8; j++) sfp[tid + j * 256] += e[j] * inv;
        __syncthreads();
    }

    for (int i = tid; i < OUTF; i += 256) atomicAdd(&fp[i], sfp[i]);
}

// ================= launch =====================================================
extern "C" void kernel_launch(void* const* d_in, const int* in_sizes, int n_in,
                              void* d_out, int out_size) {
    const float* node_attr = (const float*)d_in[0];
    const float* edge_attr = (const float*)d_in[1];
    const int*   edge_src  = (const int*)d_in[2];
    const int*   edge_dst  = (const int*)d_in[3];
    const float* W_inner   = (const float*)d_in[4];
    const float* b_inner   = (const float*)d_in[5];
    const float* W_output  = (const float*)d_in[6];
    const float* b_output  = (const float*)d_in[7];
    float* fp = (float*)d_out;

    const int n = in_sizes[0] / NODE_F;   // 50000
    const int m = in_sizes[2];            // 800000

    float *attr, *v, *logits;
    __nv_bfloat16 *Asp, *Bout, *Binn;
    cudaGetSymbolAddress((void**)&attr,   g_attr);
    cudaGetSymbolAddress((void**)&v,      g_v);
    cudaGetSymbolAddress((void**)&logits, g_logits);
    cudaGetSymbolAddress((void**)&Asp,    g_Asplit);
    cudaGetSymbolAddress((void**)&Bout,   g_Bout);
    cudaGetSymbolAddress((void**)&Binn,   g_Binn);

    cudaFuncSetAttribute(hmma_gemm_kernel,
                         cudaFuncAttributeMaxDynamicSharedMemorySize, GEMM_DSMEM);

    const int rowsM = (n + 127) / 128;            // 391
    dim3 gout(OUTF / 128, rowsM);
    dim3 ginn(DD / 128, rowsM);
    const int sm_blocks = (n + NB_SM - 1) / NB_SM;
    const int tot = n * DD;
    const size_t asp1 = (size_t)NN * DD;

    zero_fp_kernel<<<(OUTF + 255) / 256, 256>>>(fp);
    init_attr_kernel<<<(tot + 255) / 256, 256>>>(node_attr, attr, n);

    for (int d = 0; d <= DEPTH; d++) {
        __nv_bfloat16* b = Bout + (size_t)d * 2 * OUTF * DD;
        split_w_kernel<<<(OUTF * DD + 255) / 256, 256>>>(
            W_output + (size_t)d * DD * OUTF, b, b + (size_t)OUTF * DD, OUTF);
    }
    for (int d = 0; d < DEPTH; d++) {
        __nv_bfloat16* b = Binn + (size_t)d * 2 * DD * DD;
        split_w_kernel<<<(DD * DD + 255) / 256, 256>>>(
            W_inner + (size_t)d * DD * DD, b, b + (size_t)DD * DD, DD);
    }

    // depth 0
    split_attr_kernel<<<(tot + 255) / 256, 256>>>(attr, Asp, Asp + asp1, tot);
    hmma_gemm_kernel<<<gout, 256, GEMM_DSMEM>>>(
        Asp, Bout, b_output, logits, n, OUTF);
    softmax_accum_kernel<<<sm_blocks, 256>>>(logits, fp, n);

    for (int d = 1; d <= DEPTH; d++) {
        copy_v_kernel<<<(n * 64 + 255) / 256, 256>>>((const float4*)attr, (float4*)v, n * 64);
        long long etotal = (long long)m * 64;
        edge_msg_kernel<<<(int)((etotal + 255) / 256), 256>>>(
            attr, edge_attr, edge_src, edge_dst, v, m);

        // attr = v @ W_inner[d-1] + b_inner[d-1]
        split_attr_kernel<<<(tot + 255) / 256, 256>>>(v, Asp, Asp + asp1, tot);
        hmma_gemm_kernel<<<ginn, 256, GEMM_DSMEM>>>(
            Asp, Binn + (size_t)(d - 1) * 2 * DD * DD,
            b_inner + (size_t)(d - 1) * DD, attr, n, DD);

        // logits = attr @ W_output[d] + b_output[d]
        split_attr_kernel<<<(tot + 255) / 256, 256>>>(attr, Asp, Asp + asp1, tot);
        hmma_gemm_kernel<<<gout, 256, GEMM_DSMEM>>>(
            Asp, Bout + (size_t)d * 2 * OUTF * DD,
            b_output + (size_t)d * OUTF, logits, n, OUTF);
        softmax_accum_kernel<<<sm_blocks, 256>>>(logits, fp, n);
    }
}

// round 10
// speedup vs baseline: 2.1606x; 1.3776x over previous
#include <cuda_runtime.h>
#include <cuda_bf16.h>
#include <cstdint>

// Problem constants
#define NN      50000
#define NODE_F  192
#define EDGE_F  64
#define MM      800000
#define DD      256
#define OUTF    2048
#define DEPTH   3

// ---------------- scratch (static device globals; no allocation) -------------
__device__ float g_attr[(size_t)NN * DD];                 // 51.2 MB fp32
__device__ float g_logits[(size_t)NN * OUTF];             // 409.6 MB fp32
__device__ __nv_bfloat16 g_Asplit[2 * (size_t)NN * DD];   // 51.2 MB (A for out-GEMM)
__device__ __nv_bfloat16 g_Vsplit[2 * (size_t)NN * DD];   // 51.2 MB (A for inner-GEMM)
__device__ __nv_bfloat16 g_Bout[(size_t)(DEPTH + 1) * 2 * OUTF * DD]; // 8.4 MB
__device__ __nv_bfloat16 g_Binn[(size_t)DEPTH * 2 * DD * DD];         // 0.8 MB
// CSR scratch
__device__ int g_deg[NN];
__device__ int g_rowoff[NN];
__device__ int g_cursor[NN];
__device__ int g_eidx[MM];
__device__ int g_bsums[64];

// ================= small PTX helpers =========================================
__device__ __forceinline__ uint32_t smem_u32(const void* p) {
    uint32_t a;
    asm("{ .reg .u64 t; cvta.to.shared.u64 t, %1; cvt.u32.u64 %0, t; }"
        : "=r"(a) : "l"(p));
    return a;
}
__device__ __forceinline__ void cpa16(uint32_t saddr, const void* g, int srcsz) {
    asm volatile("cp.async.cg.shared.global [%0], [%1], 16, %2;"
                 :: "r"(saddr), "l"(g), "r"(srcsz));
}
#define CPA_COMMIT() asm volatile("cp.async.commit_group;" ::: "memory")
#define SWZ128(off) ((off) ^ (((off) >> 3) & 0x70))

__device__ __forceinline__ void ldsm_x4(uint32_t& r0, uint32_t& r1,
                                        uint32_t& r2, uint32_t& r3, uint32_t a) {
    asm volatile("ldmatrix.sync.aligned.m8n8.x4.shared.b16 {%0,%1,%2,%3}, [%4];"
                 : "=r"(r0), "=r"(r1), "=r"(r2), "=r"(r3) : "r"(a));
}
__device__ __forceinline__ void ldsm_x2(uint32_t& r0, uint32_t& r1, uint32_t a) {
    asm volatile("ldmatrix.sync.aligned.m8n8.x2.shared.b16 {%0,%1}, [%2];"
                 : "=r"(r0), "=r"(r1) : "r"(a));
}
__device__ __forceinline__ void mma16816(float* d, const uint32_t* a,
                                         const uint32_t* b) {
    asm volatile("mma.sync.aligned.m16n8k16.row.col.f32.bf16.bf16.f32 "
                 "{%0,%1,%2,%3}, {%4,%5,%6,%7}, {%8,%9}, {%0,%1,%2,%3};"
                 : "+f"(d[0]), "+f"(d[1]), "+f"(d[2]), "+f"(d[3])
                 : "r"(a[0]), "r"(a[1]), "r"(a[2]), "r"(a[3]),
                   "r"(b[0]), "r"(b[1]));
}

// ================= bf16 split-3 GEMM via mma.sync (HMMA) ======================
// C[M,Nc] = A_fp32 @ B + bias, via 3 bf16 split-pair passes fused into one
// K-loop of 12 chunks (BK=64). If c0 != nullptr, also emit bf16 splits of C.
#define KCH 64
#define TILE_BYTES (128 * 128)
#define STAGE_B (2 * TILE_BYTES)
#define NCHUNK 12
#define GEMM_DSMEM (1024 + 2 * STAGE_B)

__global__ __launch_bounds__(256, 2) void hmma_gemm_kernel(
        const __nv_bfloat16* __restrict__ A,
        const __nv_bfloat16* __restrict__ B,
        const float* __restrict__ bias,
        float* __restrict__ C,
        __nv_bfloat16* __restrict__ c0,   // optional split outputs
        __nv_bfloat16* __restrict__ c1,
        int Mrows, int Ncols) {
    extern __shared__ char dsm_raw[];
    __shared__ float s_bias[128];

    const int tid = threadIdx.x;
    const int wid = tid >> 5;
    const int lane = tid & 31;
    const int block_row = blockIdx.y * 128;
    const int block_col = blockIdx.x * 128;

    uint32_t dsm = smem_u32(dsm_raw);
    dsm = (dsm + 1023u) & ~1023u;

    if (tid < 128) s_bias[tid] = bias[block_col + tid];

    const int wm = wid & 1;
    const int wn = wid >> 1;

    const int sa_tab[3] = {0, 0, 1};
    const int sb_tab[3] = {0, 1, 0};
    const size_t a_split_stride = (size_t)NN * DD;
    const size_t b_split_stride = (size_t)Ncols * DD;

    float acc[4][4][4];
#pragma unroll
    for (int i = 0; i < 4; i++)
#pragma unroll
        for (int j = 0; j < 4; j++)
#pragma unroll
            for (int k = 0; k < 4; k++) acc[i][j][k] = 0.0f;

    const int ld_row = tid >> 1;
    const int ld_half = tid & 1;

    auto load_chunk = [&](int chunk, int stage) {
        int p = chunk >> 2;
        int k0 = (chunk & 3) * KCH;
        uint32_t stA = dsm + stage * STAGE_B;
        uint32_t stB = stA + TILE_BYTES;
        {
            int grow = block_row + ld_row;
            int sz = (grow < Mrows) ? 16 : 0;
            if (grow >= Mrows) grow = 0;
            const __nv_bfloat16* gsrc =
                A + sa_tab[p] * a_split_stride + (size_t)grow * DD + k0 + ld_half * 32;
#pragma unroll
            for (int t = 0; t < 4; t++) {
                uint32_t off = ld_row * 128 + ld_half * 64 + t * 16;
                cpa16(stA + SWZ128(off), gsrc + t * 8, sz);
            }
        }
        {
            int grow = block_col + ld_row;
            const __nv_bfloat16* gsrc =
                B + sb_tab[p] * b_split_stride + (size_t)grow * DD + k0 + ld_half * 32;
#pragma unroll
            for (int t = 0; t < 4; t++) {
                uint32_t off = ld_row * 128 + ld_half * 64 + t * 16;
                cpa16(stB + SWZ128(off), gsrc + t * 8, 16);
            }
        }
        CPA_COMMIT();
    };

    load_chunk(0, 0);
    load_chunk(1, 1);

    for (int i = 0; i < NCHUNK; i++) {
        int s = i & 1;
        if (i < NCHUNK - 1) asm volatile("cp.async.wait_group 1;" ::: "memory");
        else                asm volatile("cp.async.wait_group 0;" ::: "memory");
        __syncthreads();

        uint32_t stA = dsm + s * STAGE_B;
        uint32_t stB = stA + TILE_BYTES;

#pragma unroll
        for (int k = 0; k < 4; k++) {
            uint32_t af[4][4], bf[4][2];
#pragma unroll
            for (int mt = 0; mt < 4; mt++) {
                int arow = wm * 64 + mt * 16 + (lane & 15);
                uint32_t off = arow * 128 + k * 32 + ((lane >> 4) & 1) * 16;
                ldsm_x4(af[mt][0], af[mt][1], af[mt][2], af[mt][3],
                        stA + SWZ128(off));
            }
#pragma unroll
            for (int nt = 0; nt < 4; nt++) {
                int nrow = wn * 32 + nt * 8 + (lane & 7);
                uint32_t off = nrow * 128 + k * 32 + ((lane >> 3) & 1) * 16;
                ldsm_x2(bf[nt][0], bf[nt][1], stB + SWZ128(off));
            }
#pragma unroll
            for (int mt = 0; mt < 4; mt++)
#pragma unroll
                for (int nt = 0; nt < 4; nt++)
                    mma16816(acc[mt][nt], af[mt], bf[nt]);
        }
        __syncthreads();
        if (i + 2 < NCHUNK) load_chunk(i + 2, s);
    }

    const int gid = lane >> 2;
    const int tig = lane & 3;
#pragma unroll
    for (int mt = 0; mt < 4; mt++) {
#pragma unroll
        for (int half = 0; half < 2; half++) {
            int r = block_row + wm * 64 + mt * 16 + gid + half * 8;
            if (r < Mrows) {
                size_t rowbase = (size_t)r * Ncols + block_col;
                float* crow = C + rowbase;
#pragma unroll
                for (int nt = 0; nt < 4; nt++) {
                    int c = wn * 32 + nt * 8 + tig * 2;
                    float2 v;
                    v.x = acc[mt][nt][half * 2 + 0] + s_bias[c + 0];
                    v.y = acc[mt][nt][half * 2 + 1] + s_bias[c + 1];
                    *(float2*)(crow + c) = v;
                    if (c0) {
                        __nv_bfloat16 h0x = __float2bfloat16(v.x);
                        __nv_bfloat16 h0y = __float2bfloat16(v.y);
                        __nv_bfloat162 p0, p1;
                        p0.x = h0x; p0.y = h0y;
                        p1.x = __float2bfloat16(v.x - __bfloat162float(h0x));
                        p1.y = __float2bfloat16(v.y - __bfloat162float(h0y));
                        *(__nv_bfloat162*)(c0 + rowbase + c) = p0;
                        *(__nv_bfloat162*)(c1 + rowbase + c) = p1;
                    }
                }
            }
        }
    }
}

// ================= weight split ===============================================
// W [256][Ncols] fp32 -> b0,b1 [Ncols][256] bf16 (transposed, K-major)
__global__ void split_w_kernel(const float* __restrict__ W,
                               __nv_bfloat16* __restrict__ b0,
                               __nv_bfloat16* __restrict__ b1, int Ncols) {
    int i = blockIdx.x * blockDim.x + threadIdx.x;
    if (i >= Ncols * DD) return;
    int nc = i >> 8;
    int k = i & 255;
    float x = W[(size_t)k * Ncols + nc];
    __nv_bfloat16 v0 = __float2bfloat16(x);
    float res = x - __bfloat162float(v0);
    b0[i] = v0;
    b1[i] = __float2bfloat16(res);
}

// ================= CSR build ==================================================
__global__ void zero_int_kernel(int* p, int n) {
    int i = blockIdx.x * blockDim.x + threadIdx.x;
    if (i < n) p[i] = 0;
}
__global__ void hist_kernel(const int* __restrict__ edst, int* deg, int m) {
    int i = blockIdx.x * blockDim.x + threadIdx.x;
    if (i < m) atomicAdd(&deg[edst[i]], 1);
}
// per-block inclusive scan (1024 threads), emits exclusive + block sums
__global__ __launch_bounds__(1024) void scan_block_kernel(
        const int* __restrict__ deg, int* excl, int* bsums, int n) {
    __shared__ int s[1024];
    int tid = threadIdx.x;
    int gid = blockIdx.x * 1024 + tid;
    int x = (gid < n) ? deg[gid] : 0;
    s[tid] = x;
    __syncthreads();
#pragma unroll
    for (int o = 1; o < 1024; o <<= 1) {
        int t = (tid >= o) ? s[tid - o] : 0;
        __syncthreads();
        s[tid] += t;
        __syncthreads();
    }
    if (gid < n) excl[gid] = s[tid] - x;
    if (tid == 1023) bsums[blockIdx.x] = s[tid];
}
__global__ void scan_sums_kernel(int* bsums, int nb) {
    __shared__ int s[64];
    int tid = threadIdx.x;
    int x = (tid < nb) ? bsums[tid] : 0;
    s[tid] = x;
    __syncthreads();
#pragma unroll
    for (int o = 1; o < 64; o <<= 1) {
        int t = (tid >= o) ? s[tid - o] : 0;
        __syncthreads();
        s[tid] += t;
        __syncthreads();
    }
    if (tid < nb) bsums[tid] = s[tid] - x;
}
__global__ void add_off_kernel(int* excl, const int* __restrict__ bsums,
                               int* cursor, int n) {
    int i = blockIdx.x * blockDim.x + threadIdx.x;
    if (i < n) {
        int v = excl[i] + bsums[i >> 10];
        excl[i] = v;
        cursor[i] = v;
    }
}
__global__ void scatter_kernel(const int* __restrict__ edst, int* cursor,
                               int* eidx, int m) {
    int e = blockIdx.x * blockDim.x + threadIdx.x;
    if (e < m) {
        int p = atomicAdd(&cursor[edst[e]], 1);
        eidx[p] = e;
    }
}

// ================= warp-per-node aggregation + split ==========================
// v_i = attr_i + sum_{edges into i} (attr[src] + [0|edge_attr]); emit bf16 splits.
__global__ __launch_bounds__(256) void aggregate_kernel(
        const float* __restrict__ attr, const float* __restrict__ edge_attr,
        const int* __restrict__ esrc, const int* __restrict__ eidx,
        const int* __restrict__ rowoff, const int* __restrict__ deg,
        __nv_bfloat16* __restrict__ v0, __nv_bfloat16* __restrict__ v1, int n) {
    int node = (blockIdx.x * blockDim.x + threadIdx.x) >> 5;
    if (node >= n) return;
    int lane = threadIdx.x & 31;

    // lane owns cols [lane*8, lane*8+8)
    float acc[8];
    {
        const float4* arow = (const float4*)(attr + (size_t)node * DD);
        float4 a0 = arow[lane * 2], a1 = arow[lane * 2 + 1];
        acc[0] = a0.x; acc[1] = a0.y; acc[2] = a0.z; acc[3] = a0.w;
        acc[4] = a1.x; acc[5] = a1.y; acc[6] = a1.z; acc[7] = a1.w;
    }

    const int start = rowoff[node];
    const int cnt = deg[node];
    const bool has_edge = (lane >= 24);   // cols >= 192
    for (int t = 0; t < cnt; t++) {
        int eid = eidx[start + t];
        int s = esrc[eid];
        const float4* srow = (const float4*)(attr + (size_t)s * DD);
        float4 m0 = srow[lane * 2], m1 = srow[lane * 2 + 1];
        if (has_edge) {
            const float4* erow = (const float4*)(edge_attr + (size_t)eid * EDGE_F);
            float4 e0 = erow[(lane - 24) * 2];
            float4 e1 = erow[(lane - 24) * 2 + 1];
            m0.x += e0.x; m0.y += e0.y; m0.z += e0.z; m0.w += e0.w;
            m1.x += e1.x; m1.y += e1.y; m1.z += e1.z; m1.w += e1.w;
        }
        acc[0] += m0.x; acc[1] += m0.y; acc[2] += m0.z; acc[3] += m0.w;
        acc[4] += m1.x; acc[5] += m1.y; acc[6] += m1.z; acc[7] += m1.w;
    }

    __nv_bfloat16 b0[8], b1[8];
#pragma unroll
    for (int j = 0; j < 8; j++) {
        b0[j] = __float2bfloat16(acc[j]);
        b1[j] = __float2bfloat16(acc[j] - __bfloat162float(b0[j]));
    }
    size_t base = (size_t)node * DD + lane * 8;
    *(uint4*)(v0 + base) = *(uint4*)b0;
    *(uint4*)(v1 + base) = *(uint4*)b1;
}

// ================= misc kernels ===============================================
__global__ void zero_fp_kernel(float* fp) {
    int i = threadIdx.x + blockIdx.x * blockDim.x;
    if (i < OUTF) fp[i] = 0.0f;
}

// attr = [node_attr | 0]; also emit bf16 splits for depth-0 output GEMM
__global__ void init_attr_split_kernel(const float* __restrict__ node_attr,
                                       float* __restrict__ attr,
                                       __nv_bfloat16* __restrict__ a0,
                                       __nv_bfloat16* __restrict__ a1, int n) {
    int idx = threadIdx.x + blockIdx.x * blockDim.x;
    int total = n * DD;
    if (idx >= total) return;
    int i = idx >> 8;
    int k = idx & 255;
    float x = (k < NODE_F) ? node_attr[i * NODE_F + k] : 0.0f;
    attr[idx] = x;
    __nv_bfloat16 b0 = __float2bfloat16(x);
    a0[idx] = b0;
    a1[idx] = __float2bfloat16(x - __bfloat162float(b0));
}

#define NB_SM 32
__global__ __launch_bounds__(256) void softmax_accum_kernel(
        const float* __restrict__ logits, float* __restrict__ fp, int nrows) {
    __shared__ float sfp[OUTF];
    __shared__ float sredm[8];
    __shared__ float sreds[8];

    const int tid = threadIdx.x;
    const int lane = tid & 31;
    const int wid = tid >> 5;

    for (int i = tid; i < OUTF; i += 256) sfp[i] = 0.0f;
    __syncthreads();

    const int base = blockIdx.x * NB_SM;
    for (int r = 0; r < NB_SM; r++) {
        int node = base + r;
        if (node >= nrows) break;
        const float* row = logits + (size_t)node * OUTF;

        float v[8];
#pragma unroll
        for (int j = 0; j < 8; j++) v[j] = row[tid + j * 256];

        float m = v[0];
#pragma unroll
        for (int j = 1; j < 8; j++) m = fmaxf(m, v[j]);
#pragma unroll
        for (int o = 16; o; o >>= 1) m = fmaxf(m, __shfl_xor_sync(0xffffffffu, m, o));
        if (lane == 0) sredm[wid] = m;
        __syncthreads();
        m = sredm[0];
#pragma unroll
        for (int w = 1; w < 8; w++) m = fmaxf(m, sredm[w]);

        float e[8];
        float s = 0.0f;
#pragma unroll
        for (int j = 0; j < 8; j++) { e[j] = __expf(v[j] - m); s += e[j]; }
#pragma unroll
        for (int o = 16; o; o >>= 1) s += __shfl_xor_sync(0xffffffffu, s, o);
        if (lane == 0) sreds[wid] = s;
        __syncthreads();
        float st = 0.0f;
#pragma unroll
        for (int w = 0; w < 8; w++) st += sreds[w];
        float inv = 1.0f / st;

#pragma unroll
        for (int j = 0; j < 8; j++) sfp[tid + j * 256] += e[j] * inv;
        __syncthreads();
    }

    for (int i = tid; i < OUTF; i += 256) atomicAdd(&fp[i], sfp[i]);
}

// ================= launch =====================================================
extern "C" void kernel_launch(void* const* d_in, const int* in_sizes, int n_in,
                              void* d_out, int out_size) {
    const float* node_attr = (const float*)d_in[0];
    const float* edge_attr = (const float*)d_in[1];
    const int*   edge_src  = (const int*)d_in[2];
    const int*   edge_dst  = (const int*)d_in[3];
    const float* W_inner   = (const float*)d_in[4];
    const float* b_inner   = (const float*)d_in[5];
    const float* W_output  = (const float*)d_in[6];
    const float* b_output  = (const float*)d_in[7];
    float* fp = (float*)d_out;

    const int n = in_sizes[0] / NODE_F;   // 50000
    const int m = in_sizes[2];            // 800000

    float *attr, *logits;
    __nv_bfloat16 *Asp, *Vsp, *Bout, *Binn;
    int *deg, *rowoff, *cursor, *eidx, *bsums;
    cudaGetSymbolAddress((void**)&attr,   g_attr);
    cudaGetSymbolAddress((void**)&logits, g_logits);
    cudaGetSymbolAddress((void**)&Asp,    g_Asplit);
    cudaGetSymbolAddress((void**)&Vsp,    g_Vsplit);
    cudaGetSymbolAddress((void**)&Bout,   g_Bout);
    cudaGetSymbolAddress((void**)&Binn,   g_Binn);
    cudaGetSymbolAddress((void**)&deg,    g_deg);
    cudaGetSymbolAddress((void**)&rowoff, g_rowoff);
    cudaGetSymbolAddress((void**)&cursor, g_cursor);
    cudaGetSymbolAddress((void**)&eidx,   g_eidx);
    cudaGetSymbolAddress((void**)&bsums,  g_bsums);

    cudaFuncSetAttribute(hmma_gemm_kernel,
                         cudaFuncAttributeMaxDynamicSharedMemorySize, GEMM_DSMEM);

    const int rowsM = (n + 127) / 128;
    dim3 gout(OUTF / 128, rowsM);
    dim3 ginn(DD / 128, rowsM);
    const int sm_blocks = (n + NB_SM - 1) / NB_SM;
    const int tot = n * DD;
    const size_t asp1 = (size_t)NN * DD;
    const int scan_blocks = (n + 1023) / 1024;   // 49

    zero_fp_kernel<<<(OUTF + 255) / 256, 256>>>(fp);
    init_attr_split_kernel<<<(tot + 255) / 256, 256>>>(
        node_attr, attr, Asp, Asp + asp1, n);

    // weight splits
    for (int d = 0; d <= DEPTH; d++) {
        __nv_bfloat16* b = Bout + (size_t)d * 2 * OUTF * DD;
        split_w_kernel<<<(OUTF * DD + 255) / 256, 256>>>(
            W_output + (size_t)d * DD * OUTF, b, b + (size_t)OUTF * DD, OUTF);
    }
    for (int d = 0; d < DEPTH; d++) {
        __nv_bfloat16* b = Binn + (size_t)d * 2 * DD * DD;
        split_w_kernel<<<(DD * DD + 255) / 256, 256>>>(
            W_inner + (size_t)d * DD * DD, b, b + (size_t)DD * DD, DD);
    }

    // CSR build (once; edges constant across depths)
    zero_int_kernel<<<(n + 255) / 256, 256>>>(deg, n);
    hist_kernel<<<(m + 255) / 256, 256>>>(edge_dst, deg, m);
    scan_block_kernel<<<scan_blocks, 1024>>>(deg, rowoff, bsums, n);
    scan_sums_kernel<<<1, 64>>>(bsums, scan_blocks);
    add_off_kernel<<<(n + 255) / 256, 256>>>(rowoff, bsums, cursor, n);
    scatter_kernel<<<(m + 255) / 256, 256>>>(edge_dst, cursor, eidx, m);

    // depth 0
    hmma_gemm_kernel<<<gout, 256, GEMM_DSMEM>>>(
        Asp, Bout, b_output, logits, (__nv_bfloat16*)nullptr,
        (__nv_bfloat16*)nullptr, n, OUTF);
    softmax_accum_kernel<<<sm_blocks, 256>>>(logits, fp, n);

    const int agg_blocks = (n * 32 + 255) / 256;
    for (int d = 1; d <= DEPTH; d++) {
        // Vsp = splits(attr + aggregated messages)
        aggregate_kernel<<<agg_blocks, 256>>>(
            attr, edge_attr, edge_src, eidx, rowoff, deg, Vsp, Vsp + asp1, n);
        // attr = Vsp_f32 @ W_inner + b; also emit Asp splits
        hmma_gemm_kernel<<<ginn, 256, GEMM_DSMEM>>>(
            Vsp, Binn + (size_t)(d - 1) * 2 * DD * DD,
            b_inner + (size_t)(d - 1) * DD, attr, Asp, Asp + asp1, n, DD);
        // logits = attr @ W_output + b
        hmma_gemm_kernel<<<gout, 256, GEMM_DSMEM>>>(
            Asp, Bout + (size_t)d * 2 * OUTF * DD,
            b_output + (size_t)d * OUTF, logits, (__nv_bfloat16*)nullptr,
            (__nv_bfloat16*)nullptr, n, OUTF);
        softmax_accum_kernel<<<sm_blocks, 256>>>(logits, fp, n);
    }
}

// round 12
// speedup vs baseline: 2.2167x; 1.0260x over previous
#include <cuda_runtime.h>
#include <cuda_bf16.h>
#include <cstdint>

// Problem constants
#define NN      50000
#define NODE_F  192
#define EDGE_F  64
#define MM      800000
#define DD      256
#define OUTF    2048
#define DEPTH   3

// ---------------- scratch (static device globals; no allocation) -------------
__device__ float g_attr[(size_t)NN * DD];
__device__ float g_logits[(size_t)NN * OUTF];
__device__ __nv_bfloat16 g_Asplit[2 * (size_t)NN * DD];
__device__ __nv_bfloat16 g_Vsplit[2 * (size_t)NN * DD];
__device__ __nv_bfloat16 g_Bout[(size_t)(DEPTH + 1) * 2 * OUTF * DD];
__device__ __nv_bfloat16 g_Binn[(size_t)DEPTH * 2 * DD * DD];
// CSR scratch
__device__ int g_deg[NN];
__device__ int g_rowoff[NN];
__device__ int g_cursor[NN];
__device__ int g_eidx[MM];
__device__ int g_bsums[64];

// ================= small PTX helpers =========================================
__device__ __forceinline__ uint32_t smem_u32(const void* p) {
    uint32_t a;
    asm("{ .reg .u64 t; cvta.to.shared.u64 t, %1; cvt.u32.u64 %0, t; }"
        : "=r"(a) : "l"(p));
    return a;
}
__device__ __forceinline__ void cpa16(uint32_t saddr, const void* g, int srcsz) {
    asm volatile("cp.async.cg.shared.global [%0], [%1], 16, %2;"
                 :: "r"(saddr), "l"(g), "r"(srcsz));
}
#define CPA_COMMIT() asm volatile("cp.async.commit_group;" ::: "memory")
#define SWZ128(off) ((off) ^ (((off) >> 3) & 0x70))

__device__ __forceinline__ void ldsm_x4(uint32_t& r0, uint32_t& r1,
                                        uint32_t& r2, uint32_t& r3, uint32_t a) {
    asm volatile("ldmatrix.sync.aligned.m8n8.x4.shared.b16 {%0,%1,%2,%3}, [%4];"
                 : "=r"(r0), "=r"(r1), "=r"(r2), "=r"(r3) : "r"(a));
}
__device__ __forceinline__ void mma16816(float* d, const uint32_t* a,
                                         const uint32_t* b) {
    asm volatile("mma.sync.aligned.m16n8k16.row.col.f32.bf16.bf16.f32 "
                 "{%0,%1,%2,%3}, {%4,%5,%6,%7}, {%8,%9}, {%0,%1,%2,%3};"
                 : "+f"(d[0]), "+f"(d[1]), "+f"(d[2]), "+f"(d[3])
                 : "r"(a[0]), "r"(a[1]), "r"(a[2]), "r"(a[3]),
                   "r"(b[0]), "r"(b[1]));
}

// ================= bf16 split-3 GEMM via mma.sync (HMMA) ======================
#define KCH 64
#define TILE_BYTES (128 * 128)
#define STAGE_B (2 * TILE_BYTES)
#define NCHUNK 12
#define NSTAGE 3
#define GEMM_DSMEM (1024 + NSTAGE * STAGE_B)   // ~97 KB

__global__ __launch_bounds__(256, 2) void hmma_gemm_kernel(
        const __nv_bfloat16* __restrict__ A,
        const __nv_bfloat16* __restrict__ B,
        const float* __restrict__ bias,
        float* __restrict__ C,
        __nv_bfloat16* __restrict__ c0,
        __nv_bfloat16* __restrict__ c1,
        int Mrows, int Ncols) {
    extern __shared__ char dsm_raw[];
    __shared__ float s_bias[128];

    const int tid = threadIdx.x;
    const int wid = tid >> 5;
    const int lane = tid & 31;
    const int block_row = blockIdx.y * 128;
    const int block_col = blockIdx.x * 128;

    uint32_t dsm = smem_u32(dsm_raw);
    dsm = (dsm + 1023u) & ~1023u;

    if (tid < 128) s_bias[tid] = bias[block_col + tid];

    const int wm = wid & 1;
    const int wn = wid >> 1;

    const int sa_tab[3] = {0, 0, 1};
    const int sb_tab[3] = {0, 1, 0};
    const size_t a_split_stride = (size_t)NN * DD;
    const size_t b_split_stride = (size_t)Ncols * DD;

    float acc[4][4][4];
#pragma unroll
    for (int i = 0; i < 4; i++)
#pragma unroll
        for (int j = 0; j < 4; j++)
#pragma unroll
            for (int k = 0; k < 4; k++) acc[i][j][k] = 0.0f;

    const int ld_row = tid >> 1;
    const int ld_half = tid & 1;

    auto load_chunk = [&](int chunk, int stage) {
        int p = chunk >> 2;
        int k0 = (chunk & 3) * KCH;
        uint32_t stA = dsm + stage * STAGE_B;
        uint32_t stB = stA + TILE_BYTES;
        {
            int grow = block_row + ld_row;
            int sz = (grow < Mrows) ? 16 : 0;
            if (grow >= Mrows) grow = 0;
            const __nv_bfloat16* gsrc =
                A + sa_tab[p] * a_split_stride + (size_t)grow * DD + k0 + ld_half * 32;
#pragma unroll
            for (int t = 0; t < 4; t++) {
                uint32_t off = ld_row * 128 + ld_half * 64 + t * 16;
                cpa16(stA + SWZ128(off), gsrc + t * 8, sz);
            }
        }
        {
            int grow = block_col + ld_row;
            const __nv_bfloat16* gsrc =
                B + sb_tab[p] * b_split_stride + (size_t)grow * DD + k0 + ld_half * 32;
#pragma unroll
            for (int t = 0; t < 4; t++) {
                uint32_t off = ld_row * 128 + ld_half * 64 + t * 16;
                cpa16(stB + SWZ128(off), gsrc + t * 8, 16);
            }
        }
        CPA_COMMIT();
    };

    load_chunk(0, 0);
    load_chunk(1, 1);

    // B-frag x4 addressing: lanes 0-7 -> (nt, kh0), 8-15 -> (nt, kh1),
    //                       16-23 -> (nt+1, kh0), 24-31 -> (nt+1, kh1)
    const int b_nt2 = (lane >> 4) & 1;
    const int b_kh = (lane >> 3) & 1;
    const int b_r = lane & 7;

    for (int i = 0; i < NCHUNK; i++) {
        int s = i % NSTAGE;
        if (i < NCHUNK - 1) asm volatile("cp.async.wait_group 1;" ::: "memory");
        else                asm volatile("cp.async.wait_group 0;" ::: "memory");
        __syncthreads();
        // stage (i+2)%NSTAGE holds chunk i-1 (fully consumed; barrier above
        // guarantees every warp finished it) -> safe to overwrite now.
        if (i + 2 < NCHUNK) load_chunk(i + 2, (i + 2) % NSTAGE);

        uint32_t stA = dsm + s * STAGE_B;
        uint32_t stB = stA + TILE_BYTES;

#pragma unroll
        for (int k = 0; k < 4; k++) {
            uint32_t af[4][4], bf[4][2];
#pragma unroll
            for (int mt = 0; mt < 4; mt++) {
                int arow = wm * 64 + mt * 16 + (lane & 15);
                uint32_t off = arow * 128 + k * 32 + ((lane >> 4) & 1) * 16;
                ldsm_x4(af[mt][0], af[mt][1], af[mt][2], af[mt][3],
                        stA + SWZ128(off));
            }
#pragma unroll
            for (int ntb = 0; ntb < 2; ntb++) {   // nt pairs {0,1}, {2,3}
                int nrow = wn * 32 + (ntb * 2 + b_nt2) * 8 + b_r;
                uint32_t off = nrow * 128 + k * 32 + b_kh * 16;
                ldsm_x4(bf[ntb * 2][0], bf[ntb * 2][1],
                        bf[ntb * 2 + 1][0], bf[ntb * 2 + 1][1],
                        stB + SWZ128(off));
            }
#pragma unroll
            for (int mt = 0; mt < 4; mt++)
#pragma unroll
                for (int nt = 0; nt < 4; nt++)
                    mma16816(acc[mt][nt], af[mt], bf[nt]);
        }
    }

    const int gid = lane >> 2;
    const int tig = lane & 3;
#pragma unroll
    for (int mt = 0; mt < 4; mt++) {
#pragma unroll
        for (int half = 0; half < 2; half++) {
            int r = block_row + wm * 64 + mt * 16 + gid + half * 8;
            if (r < Mrows) {
                size_t rowbase = (size_t)r * Ncols + block_col;
                float* crow = C + rowbase;
#pragma unroll
                for (int nt = 0; nt < 4; nt++) {
                    int c = wn * 32 + nt * 8 + tig * 2;
                    float2 v;
                    v.x = acc[mt][nt][half * 2 + 0] + s_bias[c + 0];
                    v.y = acc[mt][nt][half * 2 + 1] + s_bias[c + 1];
                    *(float2*)(crow + c) = v;
                    if (c0) {
                        __nv_bfloat16 h0x = __float2bfloat16(v.x);
                        __nv_bfloat16 h0y = __float2bfloat16(v.y);
                        __nv_bfloat162 p0, p1;
                        p0.x = h0x; p0.y = h0y;
                        p1.x = __float2bfloat16(v.x - __bfloat162float(h0x));
                        p1.y = __float2bfloat16(v.y - __bfloat162float(h0y));
                        *(__nv_bfloat162*)(c0 + rowbase + c) = p0;
                        *(__nv_bfloat162*)(c1 + rowbase + c) = p1;
                    }
                }
            }
        }
    }
}

// ================= weight split ===============================================
__global__ void split_w_kernel(const float* __restrict__ W,
                               __nv_bfloat16* __restrict__ b0,
                               __nv_bfloat16* __restrict__ b1, int Ncols) {
    int i = blockIdx.x * blockDim.x + threadIdx.x;
    if (i >= Ncols * DD) return;
    int nc = i >> 8;
    int k = i & 255;
    float x = W[(size_t)k * Ncols + nc];
    __nv_bfloat16 v0 = __float2bfloat16(x);
    float res = x - __bfloat162float(v0);
    b0[i] = v0;
    b1[i] = __float2bfloat16(res);
}

// ================= CSR build ==================================================
__global__ void zero_int_kernel(int* p, int n) {
    int i = blockIdx.x * blockDim.x + threadIdx.x;
    if (i < n) p[i] = 0;
}
__global__ void hist_kernel(const int* __restrict__ edst, int* deg, int m) {
    int i = blockIdx.x * blockDim.x + threadIdx.x;
    if (i < m) atomicAdd(&deg[edst[i]], 1);
}
__global__ __launch_bounds__(1024) void scan_block_kernel(
        const int* __restrict__ deg, int* excl, int* bsums, int n) {
    __shared__ int s[1024];
    int tid = threadIdx.x;
    int gid = blockIdx.x * 1024 + tid;
    int x = (gid < n) ? deg[gid] : 0;
    s[tid] = x;
    __syncthreads();
#pragma unroll
    for (int o = 1; o < 1024; o <<= 1) {
        int t = (tid >= o) ? s[tid - o] : 0;
        __syncthreads();
        s[tid] += t;
        __syncthreads();
    }
    if (gid < n) excl[gid] = s[tid] - x;
    if (tid == 1023) bsums[blockIdx.x] = s[tid];
}
__global__ void scan_sums_kernel(int* bsums, int nb) {
    __shared__ int s[64];
    int tid = threadIdx.x;
    int x = (tid < nb) ? bsums[tid] : 0;
    s[tid] = x;
    __syncthreads();
#pragma unroll
    for (int o = 1; o < 64; o <<= 1) {
        int t = (tid >= o) ? s[tid - o] : 0;
        __syncthreads();
        s[tid] += t;
        __syncthreads();
    }
    if (tid < nb) bsums[tid] = s[tid] - x;
}
__global__ void add_off_kernel(int* excl, const int* __restrict__ bsums,
                               int* cursor, int n) {
    int i = blockIdx.x * blockDim.x + threadIdx.x;
    if (i < n) {
        int v = excl[i] + bsums[i >> 10];
        excl[i] = v;
        cursor[i] = v;
    }
}
__global__ void scatter_kernel(const int* __restrict__ edst, int* cursor,
                               int* eidx, int m) {
    int e = blockIdx.x * blockDim.x + threadIdx.x;
    if (e < m) {
        int p = atomicAdd(&cursor[edst[e]], 1);
        eidx[p] = e;
    }
}

// ================= warp-per-node aggregation + split ==========================
__global__ __launch_bounds__(256) void aggregate_kernel(
        const float* __restrict__ attr, const float* __restrict__ edge_attr,
        const int* __restrict__ esrc, const int* __restrict__ eidx,
        const int* __restrict__ rowoff, const int* __restrict__ deg,
        __nv_bfloat16* __restrict__ v0, __nv_bfloat16* __restrict__ v1, int n) {
    int node = (blockIdx.x * blockDim.x + threadIdx.x) >> 5;
    if (node >= n) return;
    int lane = threadIdx.x & 31;

    float acc[8];
    {
        const float4* arow = (const float4*)(attr + (size_t)node * DD);
        float4 a0 = arow[lane * 2], a1 = arow[lane * 2 + 1];
        acc[0] = a0.x; acc[1] = a0.y; acc[2] = a0.z; acc[3] = a0.w;
        acc[4] = a1.x; acc[5] = a1.y; acc[6] = a1.z; acc[7] = a1.w;
    }

    const int start = rowoff[node];
    const int cnt = deg[node];
    const bool has_edge = (lane >= 24);
    for (int t = 0; t < cnt; t++) {
        int eid = eidx[start + t];
        int s = esrc[eid];
        const float4* srow = (const float4*)(attr + (size_t)s * DD);
        float4 m0 = srow[lane * 2], m1 = srow[lane * 2 + 1];
        if (has_edge) {
            const float4* erow = (const float4*)(edge_attr + (size_t)eid * EDGE_F);
            float4 e0 = erow[(lane - 24) * 2];
            float4 e1 = erow[(lane - 24) * 2 + 1];
            m0.x += e0.x; m0.y += e0.y; m0.z += e0.z; m0.w += e0.w;
            m1.x += e1.x; m1.y += e1.y; m1.z += e1.z; m1.w += e1.w;
        }
        acc[0] += m0.x; acc[1] += m0.y; acc[2] += m0.z; acc[3] += m0.w;
        acc[4] += m1.x; acc[5] += m1.y; acc[6] += m1.z; acc[7] += m1.w;
    }

    __nv_bfloat16 b0[8], b1[8];
#pragma unroll
    for (int j = 0; j < 8; j++) {
        b0[j] = __float2bfloat16(acc[j]);
        b1[j] = __float2bfloat16(acc[j] - __bfloat162float(b0[j]));
    }
    size_t base = (size_t)node * DD + lane * 8;
    *(uint4*)(v0 + base) = *(uint4*)b0;
    *(uint4*)(v1 + base) = *(uint4*)b1;
}

// ================= misc kernels ===============================================
__global__ void zero_fp_kernel(float* fp) {
    int i = threadIdx.x + blockIdx.x * blockDim.x;
    if (i < OUTF) fp[i] = 0.0f;
}

__global__ void init_attr_split_kernel(const float* __restrict__ node_attr,
                                       float* __restrict__ attr,
                                       __nv_bfloat16* __restrict__ a0,
                                       __nv_bfloat16* __restrict__ a1, int n) {
    int idx = threadIdx.x + blockIdx.x * blockDim.x;
    int total = n * DD;
    if (idx >= total) return;
    int i = idx >> 8;
    int k = idx & 255;
    float x = (k < NODE_F) ? node_attr[i * NODE_F + k] : 0.0f;
    attr[idx] = x;
    __nv_bfloat16 b0 = __float2bfloat16(x);
    a0[idx] = b0;
    a1[idx] = __float2bfloat16(x - __bfloat162float(b0));
}

#define NB_SM 32
__global__ __launch_bounds__(256) void softmax_accum_kernel(
        const float* __restrict__ logits, float* __restrict__ fp, int nrows) {
    __shared__ float sfp[OUTF];
    __shared__ float sredm[8];
    __shared__ float sreds[8];

    const int tid = threadIdx.x;
    const int lane = tid & 31;
    const int wid = tid >> 5;

    for (int i = tid; i < OUTF; i += 256) sfp[i] = 0.0f;
    __syncthreads();

    const int base = blockIdx.x * NB_SM;
    for (int r = 0; r < NB_SM; r++) {
        int node = base + r;
        if (node >= nrows) break;
        const float* row = logits + (size_t)node * OUTF;

        float v[8];
#pragma unroll
        for (int j = 0; j < 8; j++) v[j] = row[tid + j * 256];

        float m = v[0];
#pragma unroll
        for (int j = 1; j < 8; j++) m = fmaxf(m, v[j]);
#pragma unroll
        for (int o = 16; o; o >>= 1) m = fmaxf(m, __shfl_xor_sync(0xffffffffu, m, o));
        if (lane == 0) sredm[wid] = m;
        __syncthreads();
        m = sredm[0];
#pragma unroll
        for (int w = 1; w < 8; w++) m = fmaxf(m, sredm[w]);

        float e[8];
        float s = 0.0f;
#pragma unroll
        for (int j = 0; j < 8; j++) { e[j] = __expf(v[j] - m); s += e[j]; }
#pragma unroll
        for (int o = 16; o; o >>= 1) s += __shfl_xor_sync(0xffffffffu, s, o);
        if (lane == 0) sreds[wid] = s;
        __syncthreads();
        float st = 0.0f;
#pragma unroll
        for (int w = 0; w < 8; w++) st += sreds[w];
        float inv = 1.0f / st;

#pragma unroll
        for (int j = 0; j < 8; j++) sfp[tid + j * 256] += e[j] * inv;
        __syncthreads();
    }

    for (int i = tid; i < OUTF; i += 256) atomicAdd(&fp[i], sfp[i]);
}

// ================= launch =====================================================
extern "C" void kernel_launch(void* const* d_in, const int* in_sizes, int n_in,
                              void* d_out, int out_size) {
    const float* node_attr = (const float*)d_in[0];
    const float* edge_attr = (const float*)d_in[1];
    const int*   edge_src  = (const int*)d_in[2];
    const int*   edge_dst  = (const int*)d_in[3];
    const float* W_inner   = (const float*)d_in[4];
    const float* b_inner   = (const float*)d_in[5];
    const float* W_output  = (const float*)d_in[6];
    const float* b_output  = (const float*)d_in[7];
    float* fp = (float*)d_out;

    const int n = in_sizes[0] / NODE_F;
    const int m = in_sizes[2];

    float *attr, *logits;
    __nv_bfloat16 *Asp, *Vsp, *Bout, *Binn;
    int *deg, *rowoff, *cursor, *eidx, *bsums;
    cudaGetSymbolAddress((void**)&attr,   g_attr);
    cudaGetSymbolAddress((void**)&logits, g_logits);
    cudaGetSymbolAddress((void**)&Asp,    g_Asplit);
    cudaGetSymbolAddress((void**)&Vsp,    g_Vsplit);
    cudaGetSymbolAddress((void**)&Bout,   g_Bout);
    cudaGetSymbolAddress((void**)&Binn,   g_Binn);
    cudaGetSymbolAddress((void**)&deg,    g_deg);
    cudaGetSymbolAddress((void**)&rowoff, g_rowoff);
    cudaGetSymbolAddress((void**)&cursor, g_cursor);
    cudaGetSymbolAddress((void**)&eidx,   g_eidx);
    cudaGetSymbolAddress((void**)&bsums,  g_bsums);

    cudaFuncSetAttribute(hmma_gemm_kernel,
                         cudaFuncAttributeMaxDynamicSharedMemorySize, GEMM_DSMEM);

    const int rowsM = (n + 127) / 128;
    dim3 gout(OUTF / 128, rowsM);
    dim3 ginn(DD / 128, rowsM);
    const int sm_blocks = (n + NB_SM - 1) / NB_SM;
    const int tot = n * DD;
    const size_t asp1 = (size_t)NN * DD;
    const int scan_blocks = (n + 1023) / 1024;

    // Launch order arranged so profiled launch index 5 = big out-GEMM.
    zero_fp_kernel<<<(OUTF + 255) / 256, 256>>>(fp);                      // 0
    init_attr_split_kernel<<<(tot + 255) / 256, 256>>>(
        node_attr, attr, Asp, Asp + asp1, n);                             // 1
    split_w_kernel<<<(OUTF * DD + 255) / 256, 256>>>(
        W_output, Bout, Bout + (size_t)OUTF * DD, OUTF);                  // 2
    zero_int_kernel<<<(n + 255) / 256, 256>>>(deg, n);                    // 3
    hist_kernel<<<(m + 255) / 256, 256>>>(edge_dst, deg, m);              // 4
    hmma_gemm_kernel<<<gout, 256, GEMM_DSMEM>>>(                          // 5 <- ncu
        Asp, Bout, b_output, logits, (__nv_bfloat16*)nullptr,
        (__nv_bfloat16*)nullptr, n, OUTF);
    softmax_accum_kernel<<<sm_blocks, 256>>>(logits, fp, n);

    // remaining weight splits
    for (int d = 1; d <= DEPTH; d++) {
        __nv_bfloat16* b = Bout + (size_t)d * 2 * OUTF * DD;
        split_w_kernel<<<(OUTF * DD + 255) / 256, 256>>>(
            W_output + (size_t)d * DD * OUTF, b, b + (size_t)OUTF * DD, OUTF);
    }
    for (int d = 0; d < DEPTH; d++) {
        __nv_bfloat16* b = Binn + (size_t)d * 2 * DD * DD;
        split_w_kernel<<<(DD * DD + 255) / 256, 256>>>(
            W_inner + (size_t)d * DD * DD, b, b + (size_t)DD * DD, DD);
    }

    // finish CSR build
    scan_block_kernel<<<scan_blocks, 1024>>>(deg, rowoff, bsums, n);
    scan_sums_kernel<<<1, 64>>>(bsums, scan_blocks);
    add_off_kernel<<<(n + 255) / 256, 256>>>(rowoff, bsums, cursor, n);
    scatter_kernel<<<(m + 255) / 256, 256>>>(edge_dst, cursor, eidx, m);

    const int agg_blocks = (n * 32 + 255) / 256;
    for (int d = 1; d <= DEPTH; d++) {
        aggregate_kernel<<<agg_blocks, 256>>>(
            attr, edge_attr, edge_src, eidx, rowoff, deg, Vsp, Vsp + asp1, n);
        hmma_gemm_kernel<<<ginn, 256, GEMM_DSMEM>>>(
            Vsp, Binn + (size_t)(d - 1) * 2 * DD * DD,
            b_inner + (size_t)(d - 1) * DD, attr, Asp, Asp + asp1, n, DD);
        hmma_gemm_kernel<<<gout, 256, GEMM_DSMEM>>>(
            Asp, Bout + (size_t)d * 2 * OUTF * DD,
            b_output + (size_t)d * OUTF, logits, (__nv_bfloat16*)nullptr,
            (__nv_bfloat16*)nullptr, n, OUTF);
        softmax_accum_kernel<<<sm_blocks, 256>>>(logits, fp, n);
    }
}

// round 16
// speedup vs baseline: 3.2194x; 1.4524x over previous
#include <cuda_runtime.h>
#include <cuda_fp16.h>
#include <cstdint>

// Problem constants
#define NN      50000
#define NODE_F  192
#define EDGE_F  64
#define MM      800000
#define DD      256
#define OUTF    2048
#define DEPTH   3

// ---------------- scratch (static device globals; no allocation) -------------
__device__ float g_attr[(size_t)NN * DD];                 // 51.2 MB
__device__ float g_logits[(size_t)NN * OUTF];             // 409.6 MB
__device__ __half g_Ah[(size_t)NN * DD];                  // 25.6 MB (attr fp16)
__device__ __half g_Vh[(size_t)NN * DD];                  // 25.6 MB (v fp16)
__device__ __half g_BoutH[(size_t)(DEPTH + 1) * 2 * OUTF * DD]; // 8.4 MB
__device__ __half g_BinnH[(size_t)DEPTH * 2 * DD * DD];         // 0.8 MB
// CSR scratch
__device__ int g_deg[NN];
__device__ int g_rowoff[NN];
__device__ int g_cursor[NN];
__device__ int g_eidx[MM];
__device__ int g_bsums[64];

// ================= small PTX helpers =========================================
__device__ __forceinline__ uint32_t smem_u32(const void* p) {
    uint32_t a;
    asm("{ .reg .u64 t; cvta.to.shared.u64 t, %1; cvt.u32.u64 %0, t; }"
        : "=r"(a) : "l"(p));
    return a;
}
__device__ __forceinline__ void cpa16(uint32_t saddr, const void* g, int srcsz) {
    asm volatile("cp.async.cg.shared.global [%0], [%1], 16, %2;"
                 :: "r"(saddr), "l"(g), "r"(srcsz));
}
#define CPA_COMMIT() asm volatile("cp.async.commit_group;" ::: "memory")
#define SWZ128(off) ((off) ^ (((off) >> 3) & 0x70))

__device__ __forceinline__ void ldsm_x4(uint32_t& r0, uint32_t& r1,
                                        uint32_t& r2, uint32_t& r3, uint32_t a) {
    asm volatile("ldmatrix.sync.aligned.m8n8.x4.shared.b16 {%0,%1,%2,%3}, [%4];"
                 : "=r"(r0), "=r"(r1), "=r"(r2), "=r"(r3) : "r"(a));
}
__device__ __forceinline__ void mma16816h(float* d, const uint32_t* a,
                                          const uint32_t* b) {
    asm volatile("mma.sync.aligned.m16n8k16.row.col.f32.f16.f16.f32 "
                 "{%0,%1,%2,%3}, {%4,%5,%6,%7}, {%8,%9}, {%0,%1,%2,%3};"
                 : "+f"(d[0]), "+f"(d[1]), "+f"(d[2]), "+f"(d[3])
                 : "r"(a[0]), "r"(a[1]), "r"(a[2]), "r"(a[3]),
                   "r"(b[0]), "r"(b[1]));
}

// ================= fp16 2-pass GEMM via mma.sync ==============================
// C[M,Nc] = A_f16[M,256] @ (B0 + B1)[256,Nc] + bias.
// A: single fp16 rounding of fp32 attr. B0/B1: fp16 split of fp32 weights
// ([2][Nc*256], n-major rows, K contiguous). Both B passes share the A tile.
#define KCH 64
#define TILE_BYTES (128 * 128)                 // 128 rows x 128B (64 fp16)
#define STAGE_B (3 * TILE_BYTES)               // A + B0 + B1
#define GEMM_DSMEM (1024 + 2 * STAGE_B)        // ~97 KB, 2 CTAs/SM

__global__ __launch_bounds__(256, 2) void hmma_gemm_kernel(
        const __half* __restrict__ A,
        const __half* __restrict__ B,          // split-pair base
        const float* __restrict__ bias,
        float* __restrict__ C,
        __half* __restrict__ c0,               // optional fp16 emission of C
        int Mrows, int Ncols, int kchunks) {   // kchunks: 4 normally, 3 @depth0
    extern __shared__ char dsm_raw[];
    __shared__ float s_bias[128];

    const int tid = threadIdx.x;
    const int wid = tid >> 5;
    const int lane = tid & 31;
    const int block_row = blockIdx.y * 128;
    const int block_col = blockIdx.x * 128;

    uint32_t dsm = smem_u32(dsm_raw);
    dsm = (dsm + 1023u) & ~1023u;

    if (tid < 128) s_bias[tid] = bias[block_col + tid];

    const int wm = wid & 1;
    const int wn = wid >> 1;
    const size_t b_split_stride = (size_t)Ncols * DD;

    float acc[4][4][4];
#pragma unroll
    for (int i = 0; i < 4; i++)
#pragma unroll
        for (int j = 0; j < 4; j++)
#pragma unroll
            for (int k = 0; k < 4; k++) acc[i][j][k] = 0.0f;

    const int ld_row = tid >> 1;
    const int ld_half = tid & 1;

    auto load_chunk = [&](int chunk, int stage) {
        int k0 = chunk * KCH;
        uint32_t stA = dsm + stage * STAGE_B;
        uint32_t stB0 = stA + TILE_BYTES;
        uint32_t stB1 = stB0 + TILE_BYTES;
        {   // A tile
            int grow = block_row + ld_row;
            int sz = (grow < Mrows) ? 16 : 0;
            if (grow >= Mrows) grow = 0;
            const __half* gsrc = A + (size_t)grow * DD + k0 + ld_half * 32;
#pragma unroll
            for (int t = 0; t < 4; t++) {
                uint32_t off = ld_row * 128 + ld_half * 64 + t * 16;
                cpa16(stA + SWZ128(off), gsrc + t * 8, sz);
            }
        }
        {   // B0 + B1 tiles
            int grow = block_col + ld_row;
            const __half* g0 = B + (size_t)grow * DD + k0 + ld_half * 32;
            const __half* g1 = g0 + b_split_stride;
#pragma unroll
            for (int t = 0; t < 4; t++) {
                uint32_t off = ld_row * 128 + ld_half * 64 + t * 16;
                uint32_t sw = SWZ128(off);
                cpa16(stB0 + sw, g0 + t * 8, 16);
                cpa16(stB1 + sw, g1 + t * 8, 16);
            }
        }
        CPA_COMMIT();
    };

    load_chunk(0, 0);
    load_chunk(1, 1);

    // B-frag x4 pairing: lanes 0-7 (nt,k0), 8-15 (nt,k1), 16-23 (nt+1,k0), ...
    const int b_nt2 = (lane >> 4) & 1;
    const int b_kh = (lane >> 3) & 1;
    const int b_r = lane & 7;

    for (int i = 0; i < kchunks; i++) {
        int s = i & 1;
        if (i < kchunks - 1) asm volatile("cp.async.wait_group 1;" ::: "memory");
        else                 asm volatile("cp.async.wait_group 0;" ::: "memory");
        __syncthreads();

        uint32_t stA = dsm + s * STAGE_B;
        uint32_t stB0 = stA + TILE_BYTES;
        uint32_t stB1 = stB0 + TILE_BYTES;

#pragma unroll
        for (int k = 0; k < 4; k++) {
            uint32_t af[4][4], bf[4][2];
#pragma unroll
            for (int mt = 0; mt < 4; mt++) {
                int arow = wm * 64 + mt * 16 + (lane & 15);
                uint32_t off = arow * 128 + k * 32 + ((lane >> 4) & 1) * 16;
                ldsm_x4(af[mt][0], af[mt][1], af[mt][2], af[mt][3],
                        stA + SWZ128(off));
            }
            // pass over B0
#pragma unroll
            for (int ntb = 0; ntb < 2; ntb++) {
                int nrow = wn * 32 + (ntb * 2 + b_nt2) * 8 + b_r;
                uint32_t off = nrow * 128 + k * 32 + b_kh * 16;
                ldsm_x4(bf[ntb * 2][0], bf[ntb * 2][1],
                        bf[ntb * 2 + 1][0], bf[ntb * 2 + 1][1],
                        stB0 + SWZ128(off));
            }
#pragma unroll
            for (int mt = 0; mt < 4; mt++)
#pragma unroll
                for (int nt = 0; nt < 4; nt++)
                    mma16816h(acc[mt][nt], af[mt], bf[nt]);
            // pass over B1 (same A frags, same accumulators)
#pragma unroll
            for (int ntb = 0; ntb < 2; ntb++) {
                int nrow = wn * 32 + (ntb * 2 + b_nt2) * 8 + b_r;
                uint32_t off = nrow * 128 + k * 32 + b_kh * 16;
                ldsm_x4(bf[ntb * 2][0], bf[ntb * 2][1],
                        bf[ntb * 2 + 1][0], bf[ntb * 2 + 1][1],
                        stB1 + SWZ128(off));
            }
#pragma unroll
            for (int mt = 0; mt < 4; mt++)
#pragma unroll
                for (int nt = 0; nt < 4; nt++)
                    mma16816h(acc[mt][nt], af[mt], bf[nt]);
        }
        __syncthreads();
        if (i + 2 < kchunks) load_chunk(i + 2, s);
    }

    const int gid = lane >> 2;
    const int tig = lane & 3;
#pragma unroll
    for (int mt = 0; mt < 4; mt++) {
#pragma unroll
        for (int half = 0; half < 2; half++) {
            int r = block_row + wm * 64 + mt * 16 + gid + half * 8;
            if (r < Mrows) {
                size_t rowbase = (size_t)r * Ncols + block_col;
                float* crow = C + rowbase;
#pragma unroll
                for (int nt = 0; nt < 4; nt++) {
                    int c = wn * 32 + nt * 8 + tig * 2;
                    float2 v;
                    v.x = acc[mt][nt][half * 2 + 0] + s_bias[c + 0];
                    v.y = acc[mt][nt][half * 2 + 1] + s_bias[c + 1];
                    *(float2*)(crow + c) = v;
                    if (c0) {
                        __half2 h;
                        h.x = __float2half(v.x);
                        h.y = __float2half(v.y);
                        *(__half2*)(c0 + rowbase + c) = h;
                    }
                }
            }
        }
    }
}

// ================= weight split ===============================================
// W [256][Ncols] fp32 -> B0,B1 [Ncols][256] fp16 (transposed, K-major)
__global__ void split_w_kernel(const float* __restrict__ W,
                               __half* __restrict__ b0,
                               __half* __restrict__ b1, int Ncols) {
    int i = blockIdx.x * blockDim.x + threadIdx.x;
    if (i >= Ncols * DD) return;
    int nc = i >> 8;
    int k = i & 255;
    float x = W[(size_t)k * Ncols + nc];
    __half v0 = __float2half(x);
    b0[i] = v0;
    b1[i] = __float2half(x - __half2float(v0));
}

// ================= CSR build ==================================================
__global__ void zero_int_kernel(int* p, int n) {
    int i = blockIdx.x * blockDim.x + threadIdx.x;
    if (i < n) p[i] = 0;
}
__global__ void hist_kernel(const int* __restrict__ edst, int* deg, int m) {
    int i = blockIdx.x * blockDim.x + threadIdx.x;
    if (i < m) atomicAdd(&deg[edst[i]], 1);
}
__global__ __launch_bounds__(1024) void scan_block_kernel(
        const int* __restrict__ deg, int* excl, int* bsums, int n) {
    __shared__ int s[1024];
    int tid = threadIdx.x;
    int gid = blockIdx.x * 1024 + tid;
    int x = (gid < n) ? deg[gid] : 0;
    s[tid] = x;
    __syncthreads();
#pragma unroll
    for (int o = 1; o < 1024; o <<= 1) {
        int t = (tid >= o) ? s[tid - o] : 0;
        __syncthreads();
        s[tid] += t;
        __syncthreads();
    }
    if (gid < n) excl[gid] = s[tid] - x;
    if (tid == 1023) bsums[blockIdx.x] = s[tid];
}
__global__ void scan_sums_kernel(int* bsums, int nb) {
    __shared__ int s[64];
    int tid = threadIdx.x;
    int x = (tid < nb) ? bsums[tid] : 0;
    s[tid] = x;
    __syncthreads();
#pragma unroll
    for (int o = 1; o < 64; o <<= 1) {
        int t = (tid >= o) ? s[tid - o] : 0;
        __syncthreads();
        s[tid] += t;
        __syncthreads();
    }
    if (tid < nb) bsums[tid] = s[tid] - x;
}
__global__ void add_off_kernel(int* excl, const int* __restrict__ bsums,
                               int* cursor, int n) {
    int i = blockIdx.x * blockDim.x + threadIdx.x;
    if (i < n) {
        int v = excl[i] + bsums[i >> 10];
        excl[i] = v;
        cursor[i] = v;
    }
}
__global__ void scatter_kernel(const int* __restrict__ edst, int* cursor,
                               int* eidx, int m) {
    int e = blockIdx.x * blockDim.x + threadIdx.x;
    if (e < m) {
        int p = atomicAdd(&cursor[edst[e]], 1);
        eidx[p] = e;
    }
}

// ================= warp-per-node aggregation (emit fp16) ======================
__global__ __launch_bounds__(256) void aggregate_kernel(
        const float* __restrict__ attr, const float* __restrict__ edge_attr,
        const int* __restrict__ esrc, const int* __restrict__ eidx,
        const int* __restrict__ rowoff, const int* __restrict__ deg,
        __half* __restrict__ vh, int n) {
    int node = (blockIdx.x * blockDim.x + threadIdx.x) >> 5;
    if (node >= n) return;
    int lane = threadIdx.x & 31;

    float acc[8];
    {
        const float4* arow = (const float4*)(attr + (size_t)node * DD);
        float4 a0 = arow[lane * 2], a1 = arow[lane * 2 + 1];
        acc[0] = a0.x; acc[1] = a0.y; acc[2] = a0.z; acc[3] = a0.w;
        acc[4] = a1.x; acc[5] = a1.y; acc[6] = a1.z; acc[7] = a1.w;
    }

    const int start = rowoff[node];
    const int cnt = deg[node];
    const bool has_edge = (lane >= 24);
    for (int t = 0; t < cnt; t++) {
        int eid = eidx[start + t];
        int s = esrc[eid];
        const float4* srow = (const float4*)(attr + (size_t)s * DD);
        float4 m0 = srow[lane * 2], m1 = srow[lane * 2 + 1];
        if (has_edge) {
            const float4* erow = (const float4*)(edge_attr + (size_t)eid * EDGE_F);
            float4 e0 = erow[(lane - 24) * 2];
            float4 e1 = erow[(lane - 24) * 2 + 1];
            m0.x += e0.x; m0.y += e0.y; m0.z += e0.z; m0.w += e0.w;
            m1.x += e1.x; m1.y += e1.y; m1.z += e1.z; m1.w += e1.w;
        }
        acc[0] += m0.x; acc[1] += m0.y; acc[2] += m0.z; acc[3] += m0.w;
        acc[4] += m1.x; acc[5] += m1.y; acc[6] += m1.z; acc[7] += m1.w;
    }

    __half h[8];
#pragma unroll
    for (int j = 0; j < 8; j++) h[j] = __float2half(acc[j]);
    *(uint4*)(vh + (size_t)node * DD + lane * 8) = *(uint4*)h;
}

// ================= misc kernels ===============================================
__global__ void zero_fp_kernel(float* fp) {
    int i = threadIdx.x + blockIdx.x * blockDim.x;
    if (i < OUTF) fp[i] = 0.0f;
}

__global__ void init_attr_kernel(const float* __restrict__ node_attr,
                                 float* __restrict__ attr,
                                 __half* __restrict__ ah, int n) {
    int idx = threadIdx.x + blockIdx.x * blockDim.x;
    int total = n * DD;
    if (idx >= total) return;
    int i = idx >> 8;
    int k = idx & 255;
    float x = (k < NODE_F) ? node_attr[i * NODE_F + k] : 0.0f;
    attr[idx] = x;
    ah[idx] = __float2half(x);
}

#define NB_SM 32
__global__ __launch_bounds__(256) void softmax_accum_kernel(
        const float* __restrict__ logits, float* __restrict__ fp, int nrows) {
    __shared__ float sfp[OUTF];
    __shared__ float sredm[8];
    __shared__ float sreds[8];

    const int tid = threadIdx.x;
    const int lane = tid & 31;
    const int wid = tid >> 5;

    for (int i = tid; i < OUTF; i += 256) sfp[i] = 0.0f;
    __syncthreads();

    const int base = blockIdx.x * NB_SM;
    for (int r = 0; r < NB_SM; r++) {
        int node = base + r;
        if (node >= nrows) break;
        const float* row = logits + (size_t)node * OUTF;

        float v[8];
#pragma unroll
        for (int j = 0; j < 8; j++) v[j] = row[tid + j * 256];

        float m = v[0];
#pragma unroll
        for (int j = 1; j < 8; j++) m = fmaxf(m, v[j]);
#pragma unroll
        for (int o = 16; o; o >>= 1) m = fmaxf(m, __shfl_xor_sync(0xffffffffu, m, o));
        if (lane == 0) sredm[wid] = m;
        __syncthreads();
        m = sredm[0];
#pragma unroll
        for (int w = 1; w < 8; w++) m = fmaxf(m, sredm[w]);

        float e[8];
        float s = 0.0f;
#pragma unroll
        for (int j = 0; j < 8; j++) { e[j] = __expf(v[j] - m); s += e[j]; }
#pragma unroll
        for (int o = 16; o; o >>= 1) s += __shfl_xor_sync(0xffffffffu, s, o);
        if (lane == 0) sreds[wid] = s;
        __syncthreads();
        float st = 0.0f;
#pragma unroll
        for (int w = 0; w < 8; w++) st += sreds[w];
        float inv = 1.0f / st;

#pragma unroll
        for (int j = 0; j < 8; j++) sfp[tid + j * 256] += e[j] * inv;
        __syncthreads();
    }

    for (int i = tid; i < OUTF; i += 256) atomicAdd(&fp[i], sfp[i]);
}

// ================= launch =====================================================
extern "C" void kernel_launch(void* const* d_in, const int* in_sizes, int n_in,
                              void* d_out, int out_size) {
    const float* node_attr = (const float*)d_in[0];
    const float* edge_attr = (const float*)d_in[1];
    const int*   edge_src  = (const int*)d_in[2];
    const int*   edge_dst  = (const int*)d_in[3];
    const float* W_inner   = (const float*)d_in[4];
    const float* b_inner   = (const float*)d_in[5];
    const float* W_output  = (const float*)d_in[6];
    const float* b_output  = (const float*)d_in[7];
    float* fp = (float*)d_out;

    const int n = in_sizes[0] / NODE_F;
    const int m = in_sizes[2];

    float *attr, *logits;
    __half *Ah, *Vh, *BoutH, *BinnH;
    int *deg, *rowoff, *cursor, *eidx, *bsums;
    cudaGetSymbolAddress((void**)&attr,   g_attr);
    cudaGetSymbolAddress((void**)&logits, g_logits);
    cudaGetSymbolAddress((void**)&Ah,     g_Ah);
    cudaGetSymbolAddress((void**)&Vh,     g_Vh);
    cudaGetSymbolAddress((void**)&BoutH,  g_BoutH);
    cudaGetSymbolAddress((void**)&BinnH,  g_BinnH);
    cudaGetSymbolAddress((void**)&deg,    g_deg);
    cudaGetSymbolAddress((void**)&rowoff, g_rowoff);
    cudaGetSymbolAddress((void**)&cursor, g_cursor);
    cudaGetSymbolAddress((void**)&eidx,   g_eidx);
    cudaGetSymbolAddress((void**)&bsums,  g_bsums);

    cudaFuncSetAttribute(hmma_gemm_kernel,
                         cudaFuncAttributeMaxDynamicSharedMemorySize, GEMM_DSMEM);

    const int rowsM = (n + 127) / 128;
    dim3 gout(OUTF / 128, rowsM);
    dim3 ginn(DD / 128, rowsM);
    const int sm_blocks = (n + NB_SM - 1) / NB_SM;
    const int tot = n * DD;
    const int scan_blocks = (n + 1023) / 1024;

    // Launch order: our index 3 is the profiled launch (harness preludes 2,
    // ncu -s 5 -> 6th overall). Put the big out-GEMM there.
    zero_fp_kernel<<<(OUTF + 255) / 256, 256>>>(fp);                      // 0
    init_attr_kernel<<<(tot + 255) / 256, 256>>>(node_attr, attr, Ah, n); // 1
    split_w_kernel<<<(OUTF * DD + 255) / 256, 256>>>(
        W_output, BoutH, BoutH + (size_t)OUTF * DD, OUTF);                // 2
    hmma_gemm_kernel<<<gout, 256, GEMM_DSMEM>>>(                          // 3 <- ncu
        Ah, BoutH, b_output, logits, (__half*)nullptr, n, OUTF, 3);
    softmax_accum_kernel<<<sm_blocks, 256>>>(logits, fp, n);

    // remaining weight splits
    for (int d = 1; d <= DEPTH; d++) {
        __half* b = BoutH + (size_t)d * 2 * OUTF * DD;
        split_w_kernel<<<(OUTF * DD + 255) / 256, 256>>>(
            W_output + (size_t)d * DD * OUTF, b, b + (size_t)OUTF * DD, OUTF);
    }
    for (int d = 0; d < DEPTH; d++) {
        __half* b = BinnH + (size_t)d * 2 * DD * DD;
        split_w_kernel<<<(DD * DD + 255) / 256, 256>>>(
            W_inner + (size_t)d * DD * DD, b, b + (size_t)DD * DD, DD);
    }

    // CSR build
    zero_int_kernel<<<(n + 255) / 256, 256>>>(deg, n);
    hist_kernel<<<(m + 255) / 256, 256>>>(edge_dst, deg, m);
    scan_block_kernel<<<scan_blocks, 1024>>>(deg, rowoff, bsums, n);
    scan_sums_kernel<<<1, 64>>>(bsums, scan_blocks);
    add_off_kernel<<<(n + 255) / 256, 256>>>(rowoff, bsums, cursor, n);
    scatter_kernel<<<(m + 255) / 256, 256>>>(edge_dst, cursor, eidx, m);

    const int agg_blocks = (n * 32 + 255) / 256;
    for (int d = 1; d <= DEPTH; d++) {
        aggregate_kernel<<<agg_blocks, 256>>>(
            attr, edge_attr, edge_src, eidx, rowoff, deg, Vh, n);
        // attr = v @ W_inner + b (also emits Ah fp16)
        hmma_gemm_kernel<<<ginn, 256, GEMM_DSMEM>>>(
            Vh, BinnH + (size_t)(d - 1) * 2 * DD * DD,
            b_inner + (size_t)(d - 1) * DD, attr, Ah, n, DD, 4);
        // logits = attr @ W_output + b
        hmma_gemm_kernel<<<gout, 256, GEMM_DSMEM>>>(
            Ah, BoutH + (size_t)d * 2 * OUTF * DD,
            b_output + (size_t)d * OUTF, logits, (__half*)nullptr, n, OUTF, 4);
        softmax_accum_kernel<<<sm_blocks, 256>>>(logits, fp, n);
    }
}